// round 17
// baseline (speedup 1.0000x reference)
#include <cuda_runtime.h>
#include <cuda_fp16.h>

#define NB 8192
#define NT 16
#define NK 512
#define ND 128
#define TILE_B 128
#define NBT (NB/TILE_B)          // 64 row tiles
#define CHN 128                  // codes per chunk
#define NCH (NK/CHN)             // 4 chunks
#define CQS 65024.0f             // codebook int8 scale = 512*127 (|c|<=1/512 -> +-127)
#define EPS 4e-3f                // candidate window (>11 sigma of int8 quant error)
#define LOSS_SCALE 1048576.0
#define NTH 512

typedef unsigned u32;
typedef unsigned long long u64;

// smem map (bytes)
#define SM_Z2   0                         // 128 f  (z^2)
#define SM_S2   512                       // 128 f  (2*mx/(127*CQS) per row)
#define SM_QS   1024                      // 128 f  (127/mx per row)
#define SM_C2   1536                      // 512 f
#define SM_RED  3584                      // 512 double -> 7680
#define SM_BK   7680                      // 128 int -> 8192
#define SM_FBN  8192                      // int
#define SM_FBR  8196                      // 128 int -> 8708
#define SM_FBB  8712                      // u64
#define SM_A    8720                      // qz: 128 rows x 144B
#define APSA    (128*144)                 // 18432
#define SM_B    (SM_A + APSA)             // 2 bufs x 128 rows x 144B
#define BPS     (128*144)                 // 18432
#define SM_TOT  (SM_B + 2*BPS)            // 64016

// scratch: int8 codebook [T][chunk][128][128], + exact c^2
__device__ unsigned char g_cq[NT][NCH][CHN][ND];
__device__ float  g_csq[NT * NK];
__device__ u64    g_loss;
__device__ int    g_used[NT * NK];

__device__ __forceinline__ u32 s2u(const void* p) {
    u32 a;
    asm("{ .reg .u64 t; cvta.to.shared.u64 t, %1; cvt.u32.u64 %0, t; }" : "=r"(a) : "l"(p));
    return a;
}
__device__ __forceinline__ void ldsm4(u32* r, u32 a) {
    asm volatile("ldmatrix.sync.aligned.m8n8.x4.shared.b16 {%0,%1,%2,%3}, [%4];"
        : "=r"(r[0]), "=r"(r[1]), "=r"(r[2]), "=r"(r[3]) : "r"(a));
}
// int8 MMA: D[16,8] += A[16,32] * B[8,32]^T, s32 accum (4096 MAC/instr)
__device__ __forceinline__ void mma16832(int* c, const u32* a, u32 b0, u32 b1) {
    asm volatile("mma.sync.aligned.m16n8k32.row.col.s32.s8.s8.s32 "
        "{%0,%1,%2,%3}, {%4,%5,%6,%7}, {%8,%9}, {%0,%1,%2,%3};"
        : "+r"(c[0]), "+r"(c[1]), "+r"(c[2]), "+r"(c[3])
        : "r"(a[0]), "r"(a[1]), "r"(a[2]), "r"(a[3]), "r"(b0), "r"(b1));
}
__device__ __forceinline__ void cpa16(u32 dst, const void* src) {
    asm volatile("cp.async.cg.shared.global [%0], [%1], 16;" :: "r"(dst), "l"(src));
}
__device__ __forceinline__ u32 pack4(int a, int b, int c, int d) {
    return (u32)(a & 0xff) | ((u32)(b & 0xff) << 8) | ((u32)(c & 0xff) << 16) | ((u32)(d & 0xff) << 24);
}

// NEON-order sum of squares (bit-exact match to the R4-passing kernel)
__device__ __forceinline__ float sq_neon(const float* zr) {
    float s0 = 0.f, s1 = 0.f, s2 = 0.f, s3 = 0.f;
    #pragma unroll 8
    for (int d = 0; d < ND; d += 4) {
        s0 = __fadd_rn(s0, __fmul_rn(zr[d+0], zr[d+0]));
        s1 = __fadd_rn(s1, __fmul_rn(zr[d+1], zr[d+1]));
        s2 = __fadd_rn(s2, __fmul_rn(zr[d+2], zr[d+2]));
        s3 = __fadd_rn(s3, __fmul_rn(zr[d+3], zr[d+3]));
    }
    return __fadd_rn(__fadd_rn(s0, s2), __fadd_rn(s1, s3));
}

// Exact R4 distance recipe: even/odd fma chains (== FFMA2), dot=lo+hi,
// dist = fl(fl(z2 - 2*dot) + c2). 2*dot exact.
__device__ __forceinline__ float exact_dist(const float* __restrict__ z,
                                            const float* __restrict__ c,
                                            float z2, float c2) {
    float lo = 0.f, hi = 0.f;
    #pragma unroll 16
    for (int i = 0; i < 64; i++) {
        lo = __fmaf_rn(z[2*i],   c[2*i],   lo);
        hi = __fmaf_rn(z[2*i+1], c[2*i+1], hi);
    }
    float dot = __fadd_rn(lo, hi);
    return __fadd_rn(__fsub_rn(z2, 2.0f * dot), c2);
}

// ---- prep: zero globals, int8 codebook, exact c^2 ----
__global__ __launch_bounds__(256) void vq_prep(const float* __restrict__ cbk) {
    const int tid = threadIdx.x, ch = blockIdx.x, t = blockIdx.y;
    if (ch == 0 && t == 0) {
        if (tid == 0) g_loss = 0ull;
        for (int i = tid; i < NT*NK; i += 256) g_used[i] = 0;
    }
    const int k0 = ch * CHN;
    if (tid < CHN)
        g_csq[t*NK + k0 + tid] = sq_neon(cbk + ((size_t)t*NK + k0 + tid)*ND);
    for (int j = 0; j < 16; j++) {
        int i = tid + 256*j;                 // 4096 float4 tasks
        int r = i >> 5, q = i & 31;
        float4 v = *(const float4*)(cbk + ((size_t)t*NK + k0 + r)*ND + 4*q);
        u32 w = pack4(__float2int_rn(v.x*CQS), __float2int_rn(v.y*CQS),
                      __float2int_rn(v.z*CQS), __float2int_rn(v.w*CQS));
        ((u32*)&g_cq[t][ch][r][0])[q] = w;
    }
}

// ---- main: int8 MMA candidate GEMM + exact rescore + outputs ----
__global__ __launch_bounds__(NTH, 1)
void vq_main(const float* __restrict__ z_e, const float* __restrict__ cbk,
             float* __restrict__ out)
{
    extern __shared__ unsigned char sm[];
    const u32 sb = s2u(sm);
    const int tid = threadIdx.x, lane = tid & 31, wid = tid >> 5;
    const int t = blockIdx.y, bt = blockIdx.x, b0 = bt * TILE_B;
    const int wr = wid >> 2, wc = wid & 3;
    const int wm = wr * 32, wn0 = wc * 32;

    float*  z2s = (float*)(sm + SM_Z2);
    float*  s2s = (float*)(sm + SM_S2);
    float*  qss = (float*)(sm + SM_QS);
    float*  c2s = (float*)(sm + SM_C2);
    double* red = (double*)(sm + SM_RED);
    int*    bks = (int*)(sm + SM_BK);
    int*    fbn = (int*)(sm + SM_FBN);
    int*    fbr = (int*)(sm + SM_FBR);
    u64*    fbb = (u64*)(sm + SM_FBB);

    if (tid == 0) *fbn = 0;

    // issue B chunk 0 and 1 loads (cp.async, two commit groups)
    #pragma unroll 1
    for (int pre = 0; pre < 2; pre++) {
        #pragma unroll
        for (int j = 0; j < 2; j++) {
            int i = tid + NTH*j;             // 1024 x 16B per chunk
            int r = i >> 3, sg = i & 7;
            u32 dst = sb + SM_B + (u32)pre*BPS + (u32)r*144 + (u32)sg*16;
            cpa16(dst, (const char*)&g_cq[t][pre][r][0] + sg*16);
        }
        asm volatile("cp.async.commit_group;" ::: "memory");
    }

    // phase 1: per-row z^2 (exact NEON order) + row max -> scales
    if (tid < TILE_B) {
        const float* zr = z_e + ((size_t)(b0+tid)*NT + t)*ND;
        float s0 = 0.f, s1 = 0.f, s2 = 0.f, s3 = 0.f, mx = 0.f;
        #pragma unroll 8
        for (int d = 0; d < ND; d += 4) {
            float a = zr[d], b = zr[d+1], c = zr[d+2], e = zr[d+3];
            s0 = __fadd_rn(s0, __fmul_rn(a, a));
            s1 = __fadd_rn(s1, __fmul_rn(b, b));
            s2 = __fadd_rn(s2, __fmul_rn(c, c));
            s3 = __fadd_rn(s3, __fmul_rn(e, e));
            mx = fmaxf(mx, fmaxf(fmaxf(fabsf(a), fabsf(b)), fmaxf(fabsf(c), fabsf(e))));
        }
        z2s[tid] = __fadd_rn(__fadd_rn(s0, s2), __fadd_rn(s1, s3));
        float qs = 127.0f / mx;
        qss[tid] = qs;
        s2s[tid] = 2.0f * mx / (127.0f * CQS);
    }
    if (tid < NK) c2s[tid] = g_csq[t*NK + tid];
    __syncthreads();

    // phase 2: quantize A tile to int8 smem (rows hot in L1)
    #pragma unroll
    for (int j = 0; j < 8; j++) {
        int i = tid + NTH*j;                 // 4096 u32 tasks
        int r = i >> 5, q = i & 31;
        float4 v = *(const float4*)(z_e + ((size_t)(b0+r)*NT + t)*ND + 4*q);
        float qs = qss[r];
        u32 w = pack4(__float2int_rn(v.x*qs), __float2int_rn(v.y*qs),
                      __float2int_rn(v.z*qs), __float2int_rn(v.w*qs));
        *(u32*)(sm + SM_A + r*144 + 4*q) = w;
    }

    // per-thread ldmatrix base addresses (s8-k32 fragments == f16-k16 byte layout)
    const u32 aad0 = sb + SM_A + (u32)(wm + (lane & 15))*144 + (u32)(lane >> 4)*16;
    const u32 aad1 = aad0 + 16u*144;
    const u32 brow = (u32)(wn0 + (lane & 7) + ((lane >> 4) << 3));
    const u32 bof  = brow*144 + (u32)((lane >> 3) & 1)*16;

    // per-thread top-2 keys for each of the thread's 4 row-fragments
    u64 bst0[2][2], bst1[2][2];
    #pragma unroll
    for (int a = 0; a < 2; a++)
        #pragma unroll
        for (int b = 0; b < 2; b++) { bst0[a][b] = ~0ull; bst1[a][b] = ~0ull; }

    #pragma unroll 1
    for (int c = 0; c < NCH; c++) {
        if (c < NCH-1) asm volatile("cp.async.wait_group 1;" ::: "memory");
        else           asm volatile("cp.async.wait_group 0;" ::: "memory");
        __syncthreads();

        int acc[2][4][4];
        #pragma unroll
        for (int mf = 0; mf < 2; mf++)
            #pragma unroll
            for (int nf = 0; nf < 4; nf++)
                #pragma unroll
                for (int e = 0; e < 4; e++) acc[mf][nf][e] = 0;

        const u32 pb = sb + SM_B + (u32)(c & 1)*BPS + bof;

        #pragma unroll
        for (int ks = 0; ks < 4; ks++) {     // k32 steps: 4 x 32 int8 = 128
            u32 af0[4], af1[4], bf[2][4];
            ldsm4(af0, aad0 + (u32)ks*32);
            ldsm4(af1, aad1 + (u32)ks*32);
            ldsm4(bf[0], pb + (u32)ks*32);
            ldsm4(bf[1], pb + 16u*144 + (u32)ks*32);
            mma16832(acc[0][0], af0, bf[0][0], bf[0][1]);
            mma16832(acc[0][1], af0, bf[0][2], bf[0][3]);
            mma16832(acc[0][2], af0, bf[1][0], bf[1][1]);
            mma16832(acc[0][3], af0, bf[1][2], bf[1][3]);
            mma16832(acc[1][0], af1, bf[0][0], bf[0][1]);
            mma16832(acc[1][1], af1, bf[0][2], bf[0][3]);
            mma16832(acc[1][2], af1, bf[1][0], bf[1][1]);
            mma16832(acc[1][3], af1, bf[1][2], bf[1][3]);
        }

        // approx distances + running per-thread top-2 (u64 key: dist bits || idx)
        #pragma unroll
        for (int mf = 0; mf < 2; mf++)
            #pragma unroll
            for (int h = 0; h < 2; h++) {
                int rloc = wm + 16*mf + (lane >> 2) + 8*h;
                float z2v = z2s[rloc], s2v = s2s[rloc];
                u64 b0k = bst0[mf][h], b1k = bst1[mf][h];
                #pragma unroll
                for (int nf = 0; nf < 4; nf++) {
                    int colg = c*CHN + wn0 + 8*nf + (lane & 3)*2;
                    #pragma unroll
                    for (int e = 0; e < 2; e++) {
                        float dq = (float)acc[mf][nf][2*h + e];
                        float dist = __fadd_rn(__fmaf_rn(-dq, s2v, z2v), c2s[colg + e]);
                        u64 key = ((u64)__float_as_uint(dist) << 32) | (u32)(colg + e);
                        if (key < b1k) {
                            if (key < b0k) { b1k = b0k; b0k = key; }
                            else b1k = key;
                        }
                    }
                }
                bst0[mf][h] = b0k; bst1[mf][h] = b1k;
            }

        __syncthreads();                     // all warps done reading buf before refill
        if (c + 2 < NCH) {
            #pragma unroll
            for (int j = 0; j < 2; j++) {
                int i = tid + NTH*j;
                int r = i >> 3, sg = i & 7;
                u32 dst = sb + SM_B + (u32)(c & 1)*BPS + (u32)r*144 + (u32)sg*16;
                cpa16(dst, (const char*)&g_cq[t][c+2][r][0] + sg*16);
            }
            asm volatile("cp.async.commit_group;" ::: "memory");
        }
    }

    // gather: 32 keys per row (16 threads x top-2), into dead B-buffer smem
    u64* cand = (u64*)(sm + SM_B);           // 128 rows * 32 keys = 32 KB
    #pragma unroll
    for (int mf = 0; mf < 2; mf++)
        #pragma unroll
        for (int h = 0; h < 2; h++) {
            int row = wm + 16*mf + 8*h + (lane >> 2);
            int slot = wc*8 + (lane & 3)*2;
            cand[row*32 + slot]     = bst0[mf][h];
            cand[row*32 + slot + 1] = bst1[mf][h];
        }
    __syncthreads();

    // resolve per row: find approx min, certify, exact-rescore candidates
    if (tid < TILE_B) {
        const int row = tid, b = b0 + row;
        const u64* ck = cand + row*32;
        u64 mn = ck[0];
        #pragma unroll
        for (int j = 1; j < 32; j++) if (ck[j] < mn) mn = ck[j];
        const float thr = __uint_as_float((u32)(mn >> 32)) + EPS;

        bool fb = false;
        #pragma unroll
        for (int p = 0; p < 16; p++)
            if (__uint_as_float((u32)(ck[2*p+1] >> 32)) <= thr) fb = true;

        if (fb) {
            int s = atomicAdd(fbn, 1);
            fbr[s] = row;
        } else {
            int ncand = 0;
            #pragma unroll
            for (int j = 0; j < 32; j++)
                if (__uint_as_float((u32)(ck[j] >> 32)) <= thr) ncand++;
            if (ncand <= 1) {
                bks[row] = (int)(mn & 0xffffffffu);
            } else {
                const float* zp = z_e + ((size_t)b*NT + t)*ND;
                const float z2 = z2s[row];
                u64 ebest = ~0ull;
                for (int j = 0; j < 32; j++) {
                    if (__uint_as_float((u32)(ck[j] >> 32)) > thr) continue;
                    int k = (int)(ck[j] & 0xffffffffu);
                    float ed = exact_dist(zp, cbk + ((size_t)t*NK + k)*ND, z2, c2s[k]);
                    u64 ek = ((u64)__float_as_uint(ed) << 32) | (u32)k;
                    if (ek < ebest) ebest = ek;
                }
                bks[row] = (int)(ebest & 0xffffffffu);
            }
        }
    }
    __syncthreads();

    // cooperative exact fallback for uncertified rows: 512 codes, 1/thread
    {
        const int nfb = *fbn;
        for (int f = 0; f < nfb; f++) {
            if (tid == 0) *fbb = ~0ull;
            __syncthreads();
            const int row = fbr[f], b = b0 + row;
            const float* zp = z_e + ((size_t)b*NT + t)*ND;
            const float z2 = z2s[row];
            const int k = tid;
            float ed = exact_dist(zp, cbk + ((size_t)t*NK + k)*ND, z2, c2s[k]);
            u64 loc = ((u64)__float_as_uint(ed) << 32) | (u32)k;
            #pragma unroll
            for (int off = 16; off >= 1; off >>= 1) {
                u64 o = __shfl_xor_sync(0xffffffffu, loc, off);
                if (o < loc) loc = o;
            }
            if (lane == 0) atomicMin(fbb, loc);
            __syncthreads();
            if (tid == 0) bks[row] = (int)(*fbb & 0xffffffffu);
            __syncthreads();
        }
    }
    __syncthreads();

    // tokens + usage
    if (tid < TILE_B) {
        int bk = bks[tid], b = b0 + tid;
        out[(size_t)NB*NT*ND + (size_t)b*NT + t] = (float)bk;
        g_used[t*NK + bk] = 1;
    }
    __syncthreads();

    // z_q_st + loss: 4 threads per row (32 floats each), R4-identical rounding
    {
        int row = tid >> 2, quad = tid & 3;
        int b = b0 + row, bk = bks[row];
        const float4* zr = (const float4*)(z_e + ((size_t)b*NT + t)*ND + quad*32);
        const float4* cr = (const float4*)(cbk + ((size_t)t*NK + bk)*ND + quad*32);
        float4* orow = (float4*)(out + ((size_t)b*NT + t)*ND + quad*32);
        double ls = 0.0;
        #pragma unroll
        for (int q = 0; q < 8; q++) {
            float4 zv = zr[q], cv = cr[q], ov;
            ov.x = __fadd_rn(zv.x, __fsub_rn(cv.x, zv.x)); { float d = __fsub_rn(zv.x, cv.x); ls += (double)__fmul_rn(d, d); }
            ov.y = __fadd_rn(zv.y, __fsub_rn(cv.y, zv.y)); { float d = __fsub_rn(zv.y, cv.y); ls += (double)__fmul_rn(d, d); }
            ov.z = __fadd_rn(zv.z, __fsub_rn(cv.z, zv.z)); { float d = __fsub_rn(zv.z, cv.z); ls += (double)__fmul_rn(d, d); }
            ov.w = __fadd_rn(zv.w, __fsub_rn(cv.w, zv.w)); { float d = __fsub_rn(zv.w, cv.w); ls += (double)__fmul_rn(d, d); }
            orow[q] = ov;
        }
        red[tid] = ls;
    }
    __syncthreads();
    for (int s = 256; s > 0; s >>= 1) {
        if (tid < s) red[tid] += red[tid + s];
        __syncthreads();
    }
    if (tid == 0) {
        long long q = __double2ll_rn(red[0] * LOSS_SCALE);
        atomicAdd(&g_loss, (u64)q);
    }
}

__global__ void vq_fin(float* __restrict__ out) {
    __shared__ int cnt[256];
    int tid = threadIdx.x;
    int c = 0;
    for (int i = tid; i < NT*NK; i += 256) c += g_used[i];
    cnt[tid] = c;
    __syncthreads();
    for (int s = 128; s > 0; s >>= 1) {
        if (tid < s) cnt[tid] += cnt[tid + s];
        __syncthreads();
    }
    if (tid == 0) {
        double ls = (double)g_loss / LOSS_SCALE;
        float vql = (float)(0.25 * ls / ((double)NB * NT * ND));
        size_t base = (size_t)NB*NT*ND + (size_t)NB*NT;
        out[base]     = vql;
        out[base + 1] = (float)cnt[0] / (float)(NT * NK);
    }
}

extern "C" void kernel_launch(void* const* d_in, const int* in_sizes, int n_in,
                              void* d_out, int out_size)
{
    const float* z_e = (const float*)d_in[0];   // (B, T, D) fp32
    const float* cbk = (const float*)d_in[1];   // (T, K, D) fp32
    float* out = (float*)d_out;

    cudaFuncSetAttribute(vq_main, cudaFuncAttributeMaxDynamicSharedMemorySize, SM_TOT);

    vq_prep<<<dim3(NCH, NT), 256>>>(cbk);
    vq_main<<<dim3(NBT, NT), NTH, SM_TOT>>>(z_e, cbk, out);
    vq_fin<<<1, 256>>>(out);
}